// round 1
// baseline (speedup 1.0000x reference)
#include <cuda_runtime.h>
#include <cuda_bf16.h>

// NormalsRenderer: B=512 batches, N=512 points each.
// out[b] = normalize( sum_i ( sum_{j!=i} exp(-acos(clip(dot(n_i,n_j)))) ) * n_i )
// (global-max scaling in the reference cancels under normalization; EPS never binds)

#define B_BATCH 512
#define NPTS    512

__global__ __launch_bounds__(NPTS)
void normals_renderer_kernel(const float* __restrict__ normals,
                             float* __restrict__ out)
{
    __shared__ float4 sn[NPTS];     // normals of this batch (w unused, for LDS.128)
    __shared__ float4 sred[NPTS];   // reduction buffer

    const int b = blockIdx.x;
    const int i = threadIdx.x;

    const float* base = normals + (size_t)b * NPTS * 3;
    const float x = base[i * 3 + 0];
    const float y = base[i * 3 + 1];
    const float z = base[i * 3 + 2];
    sn[i] = make_float4(x, y, z, 0.0f);
    __syncthreads();

    // acos(x) ~= sqrt(1-|x|) * poly3(|x|), sign-fixed; max abs err ~6.8e-5.
    const float a0 =  1.5707288f;
    const float a1 = -0.2121144f;
    const float a2 =  0.0742610f;
    const float a3 = -0.0187293f;
    const float PI = 3.14159265358979323846f;

    float acc = 0.0f;
    #pragma unroll 8
    for (int j = 0; j < NPTS; ++j) {
        float4 nj = sn[j];                      // broadcast LDS.128 (all lanes same j)
        float d = x * nj.x;
        d = fmaf(y, nj.y, d);
        d = fmaf(z, nj.z, d);
        d = fminf(1.0f, fmaxf(-1.0f, d));
        float ax = fabsf(d);
        float p = fmaf(fmaf(fmaf(a3, ax, a2), ax, a1), ax, a0);
        float r = p * sqrtf(1.0f - ax);
        float ac = (d >= 0.0f) ? r : (PI - r);
        acc += __expf(-ac);
    }

    // Subtract the j == i term (computed through the identical code path so it
    // cancels the loop's contribution to rounding).
    {
        float d = x * x;
        d = fmaf(y, y, d);
        d = fmaf(z, z, d);
        d = fminf(1.0f, fmaxf(-1.0f, d));
        float ax = fabsf(d);
        float p = fmaf(fmaf(fmaf(a3, ax, a2), ax, a1), ax, a0);
        float r = p * sqrtf(1.0f - ax);
        float ac = (d >= 0.0f) ? r : (PI - r);
        acc -= __expf(-ac);
    }

    // Weighted sum over i: n = sum_i acc_i * n_i  (block tree reduction)
    sred[i] = make_float4(acc * x, acc * y, acc * z, 0.0f);
    __syncthreads();

    #pragma unroll
    for (int s = NPTS / 2; s >= 1; s >>= 1) {
        if (i < s) {
            float4 a  = sred[i];
            float4 bb = sred[i + s];
            sred[i] = make_float4(a.x + bb.x, a.y + bb.y, a.z + bb.z, 0.0f);
        }
        __syncthreads();
    }

    if (i == 0) {
        float4 v = sred[0];
        float ss = v.x * v.x + v.y * v.y + v.z * v.z;
        float inv = rsqrtf(fmaxf(ss, 1e-20f));
        out[b * 3 + 0] = v.x * inv;
        out[b * 3 + 1] = v.y * inv;
        out[b * 3 + 2] = v.z * inv;
    }
}

extern "C" void kernel_launch(void* const* d_in, const int* in_sizes, int n_in,
                              void* d_out, int out_size)
{
    const float* normals = (const float*)d_in[0];  // [512, 512, 3] f32
    // d_in[1] = weights: unused by the reference math.
    float* out = (float*)d_out;                    // [512, 3] f32

    normals_renderer_kernel<<<B_BATCH, NPTS>>>(normals, out);
}

// round 2
// speedup vs baseline: 2.2544x; 2.2544x over previous
#include <cuda_runtime.h>
#include <cuda_bf16.h>

// NormalsRenderer: B=512, N=512.
// out[b] = normalize( sum_i acc_i * n_i ),  acc_i = sum_{j!=i} exp(-acos(clip(<n_i,n_j>)))
// Identities used (uniform positive scales cancel under the final normalize):
//   - division by max(new_weights) dropped
//   - exp(-acos d) = e^{-pi/2} * exp(asin d); the e^{-pi/2} factor dropped
//   - exp(asin d) = exp2( copysign( L*pi/2 - sqrt(1-ax)*L*p(ax), d ) ),  ax = min(|d|,1)
//     with A&S 4.4.45 poly p (abs err ~6.8e-5), L = log2(e) folded into the coefficients.

#define NPTS 512
#define TPB  256
#define B_BATCH 512

typedef unsigned long long ull;

// log2(e)-scaled, sign-baked A&S coefficients: poly(ax) = -L*p(ax)
#define C0f (-2.26608253f)
#define C1f ( 0.30601639f)
#define C2f (-0.10713599f)
#define C3f ( 0.02702067f)
#define LHPI ( 2.26618007f)   // L * pi/2

__device__ __forceinline__ ull pack2(float lo, float hi) {
    ull r; asm("mov.b64 %0, {%1, %2};" : "=l"(r) : "f"(lo), "f"(hi)); return r;
}
__device__ __forceinline__ void unpack2(ull v, float& lo, float& hi) {
    asm("mov.b64 {%0, %1}, %2;" : "=f"(lo), "=f"(hi) : "l"(v));
}
__device__ __forceinline__ ull fma2(ull a, ull b, ull c) {
    ull d; asm("fma.rn.f32x2 %0, %1, %2, %3;" : "=l"(d) : "l"(a), "l"(b), "l"(c)); return d;
}
__device__ __forceinline__ ull mul2(ull a, ull b) {
    ull d; asm("mul.rn.f32x2 %0, %1, %2;" : "=l"(d) : "l"(a), "l"(b)); return d;
}
__device__ __forceinline__ ull add2(ull a, ull b) {
    ull d; asm("add.rn.f32x2 %0, %1, %2;" : "=l"(d) : "l"(a), "l"(b)); return d;
}
__device__ __forceinline__ float sqrta(float x) {
    float r; asm("sqrt.approx.f32 %0, %1;" : "=f"(r) : "f"(x)); return r;
}
__device__ __forceinline__ float ex2a(float x) {
    float r; asm("ex2.approx.f32 %0, %1;" : "=f"(r) : "f"(x)); return r;
}

// Self-term (j == i): d = |n|^2 >= 0, so no copysign. Must mirror the packed
// loop's op order exactly so the subtraction cancels the loop contribution.
__device__ __forceinline__ float self_w(float x, float y, float z) {
    float d  = fmaf(z, z, fmaf(y, y, x * x));
    float ax = fminf(fabsf(d), 1.0f);
    float sq = sqrta(1.0f - ax);
    float p  = fmaf(ax, C3f, C2f);
    p = fmaf(ax, p, C1f);
    p = fmaf(ax, p, C0f);
    float g = fmaf(sq, p, LHPI);
    return ex2a(g);
}

__global__ __launch_bounds__(TPB)
void normals_renderer_kernel(const float* __restrict__ normals,
                             float* __restrict__ out)
{
    __shared__ float2 snx[NPTS / 2], sny[NPTS / 2], snz[NPTS / 2];
    __shared__ float  sw[3][TPB / 32];

    const int b  = blockIdx.x;
    const int t  = threadIdx.x;
    const int i0 = t;
    const int i1 = t + TPB;

    const float* base = normals + (size_t)b * NPTS * 3;
    const float x0 = base[i0 * 3 + 0], y0 = base[i0 * 3 + 1], z0 = base[i0 * 3 + 2];
    const float x1 = base[i1 * 3 + 0], y1 = base[i1 * 3 + 1], z1 = base[i1 * 3 + 2];

    ((float*)snx)[i0] = x0; ((float*)snx)[i1] = x1;
    ((float*)sny)[i0] = y0; ((float*)sny)[i1] = y1;
    ((float*)snz)[i0] = z0; ((float*)snz)[i1] = z1;
    __syncthreads();

    const ull x20 = pack2(x0, x0), y20 = pack2(y0, y0), z20 = pack2(z0, z0);
    const ull x21 = pack2(x1, x1), y21 = pack2(y1, y1), z21 = pack2(z1, z1);
    const ull c3v = pack2(C3f, C3f), c2v = pack2(C2f, C2f);
    const ull c1v = pack2(C1f, C1f), c0v = pack2(C0f, C0f);
    const ull lh2 = pack2(LHPI, LHPI);

    ull acc0 = pack2(0.0f, 0.0f);
    ull acc1 = pack2(0.0f, 0.0f);

    const ull* __restrict__ px = (const ull*)snx;
    const ull* __restrict__ py = (const ull*)sny;
    const ull* __restrict__ pz = (const ull*)snz;

    #pragma unroll 4
    for (int tj = 0; tj < NPTS / 2; ++tj) {
        const ull njx = px[tj];    // broadcast LDS.64 (all lanes same tj)
        const ull njy = py[tj];
        const ull njz = pz[tj];

        // ---- row i0, j-pair ----
        {
            ull d2 = fma2(z20, njz, fma2(y20, njy, mul2(x20, njx)));
            float da, db; unpack2(d2, da, db);
            float axa = fminf(fabsf(da), 1.0f);
            float axb = fminf(fabsf(db), 1.0f);
            float sqa = sqrta(1.0f - axa);
            float sqb = sqrta(1.0f - axb);
            ull ax2 = pack2(axa, axb);
            ull p2  = fma2(ax2, c3v, c2v);
            p2 = fma2(ax2, p2, c1v);
            p2 = fma2(ax2, p2, c0v);
            ull g2 = fma2(pack2(sqa, sqb), p2, lh2);
            float ga, gb; unpack2(g2, ga, gb);
            unsigned int ea = __float_as_uint(ga) | (__float_as_uint(da) & 0x80000000u);
            unsigned int eb = __float_as_uint(gb) | (__float_as_uint(db) & 0x80000000u);
            acc0 = add2(acc0, pack2(ex2a(__uint_as_float(ea)), ex2a(__uint_as_float(eb))));
        }
        // ---- row i1, same j-pair ----
        {
            ull d2 = fma2(z21, njz, fma2(y21, njy, mul2(x21, njx)));
            float da, db; unpack2(d2, da, db);
            float axa = fminf(fabsf(da), 1.0f);
            float axb = fminf(fabsf(db), 1.0f);
            float sqa = sqrta(1.0f - axa);
            float sqb = sqrta(1.0f - axb);
            ull ax2 = pack2(axa, axb);
            ull p2  = fma2(ax2, c3v, c2v);
            p2 = fma2(ax2, p2, c1v);
            p2 = fma2(ax2, p2, c0v);
            ull g2 = fma2(pack2(sqa, sqb), p2, lh2);
            float ga, gb; unpack2(g2, ga, gb);
            unsigned int ea = __float_as_uint(ga) | (__float_as_uint(da) & 0x80000000u);
            unsigned int eb = __float_as_uint(gb) | (__float_as_uint(db) & 0x80000000u);
            acc1 = add2(acc1, pack2(ex2a(__uint_as_float(ea)), ex2a(__uint_as_float(eb))));
        }
    }

    float a0l, a0h, a1l, a1h;
    unpack2(acc0, a0l, a0h);
    unpack2(acc1, a1l, a1h);
    const float w0 = (a0l + a0h) - self_w(x0, y0, z0);
    const float w1 = (a1l + a1h) - self_w(x1, y1, z1);

    // Local weighted contribution of both rows, then block reduce.
    float vx = fmaf(w1, x1, w0 * x0);
    float vy = fmaf(w1, y1, w0 * y0);
    float vz = fmaf(w1, z1, w0 * z0);

    #pragma unroll
    for (int s = 16; s >= 1; s >>= 1) {
        vx += __shfl_down_sync(0xffffffffu, vx, s);
        vy += __shfl_down_sync(0xffffffffu, vy, s);
        vz += __shfl_down_sync(0xffffffffu, vz, s);
    }
    const int lane = t & 31, warp = t >> 5;
    if (lane == 0) { sw[0][warp] = vx; sw[1][warp] = vy; sw[2][warp] = vz; }
    __syncthreads();

    if (warp == 0) {
        float rx = (lane < TPB / 32) ? sw[0][lane] : 0.0f;
        float ry = (lane < TPB / 32) ? sw[1][lane] : 0.0f;
        float rz = (lane < TPB / 32) ? sw[2][lane] : 0.0f;
        #pragma unroll
        for (int s = 4; s >= 1; s >>= 1) {
            rx += __shfl_down_sync(0xffffffffu, rx, s);
            ry += __shfl_down_sync(0xffffffffu, ry, s);
            rz += __shfl_down_sync(0xffffffffu, rz, s);
        }
        if (lane == 0) {
            float ss  = fmaf(rx, rx, fmaf(ry, ry, rz * rz));
            float inv = rsqrtf(fmaxf(ss, 1e-20f));
            out[b * 3 + 0] = rx * inv;
            out[b * 3 + 1] = ry * inv;
            out[b * 3 + 2] = rz * inv;
        }
    }
}

extern "C" void kernel_launch(void* const* d_in, const int* in_sizes, int n_in,
                              void* d_out, int out_size)
{
    const float* normals = (const float*)d_in[0];  // [512, 512, 3] f32
    // d_in[1] = weights: unused by the reference math.
    float* out = (float*)d_out;                    // [512, 3] f32

    normals_renderer_kernel<<<B_BATCH, TPB>>>(normals, out);
}

// round 3
// speedup vs baseline: 2.6412x; 1.1716x over previous
#include <cuda_runtime.h>
#include <cuda_bf16.h>

// NormalsRenderer: B=512, N=512.
// out[b] = normalize( sum_i acc_i * n_i ),  acc_i = sum_{j!=i} exp(-acos(clip(<n_i,n_j>)))
// Identities (uniform positive scales cancel under the final normalize):
//   - division by max(new_weights) dropped
//   - exp(-acos d) = e^{-pi/2} * exp(asin d); constant factor dropped
//   - with u = sat(1 - |d|)  (single FADD.SAT; equals clip+abs),
//     asin(|d|)*log2(e) = LHPI + sqrt(u)*Q(u),  Q = cubic (A&S 4.4.45 re-expanded in u)
//     w = exp2( copysign( LHPI + sqrt(u)*Q(u), d ) )
// Symmetry: w_ij = w_ji. Cyclic-offset schedule evaluates each unordered pair once:
//   o = 1..255: thread t (rows i0=t, i1=t+256) computes pairs (i0, k) and (i1, k^256),
//   k = t+o; adds locally and "gifts" the same weights to rows k / k^256 via smem
//   (partner thread k&255, halves swapped when k>=256). o=256 pairs a thread's own rows.

#define NPTS 512
#define TPB  256
#define B_BATCH 512

typedef unsigned long long ull;

// -L * p_AS(1-u) coefficients (poly in u), and L*pi/2
#define Q0f (-2.0401824f)
#define Q1f (-0.17280645f)
#define Q2f (-0.026074023f)
#define Q3f (-0.027020667f)
#define LHPIf (2.2661800709f)

__device__ __forceinline__ ull pack2(float lo, float hi) {
    ull r; asm("mov.b64 %0, {%1, %2};" : "=l"(r) : "f"(lo), "f"(hi)); return r;
}
__device__ __forceinline__ void unpack2(ull v, float& lo, float& hi) {
    asm("mov.b64 {%0, %1}, %2;" : "=f"(lo), "=f"(hi) : "l"(v));
}
__device__ __forceinline__ ull fma2(ull a, ull b, ull c) {
    ull d; asm("fma.rn.f32x2 %0, %1, %2, %3;" : "=l"(d) : "l"(a), "l"(b), "l"(c)); return d;
}
__device__ __forceinline__ ull mul2(ull a, ull b) {
    ull d; asm("mul.rn.f32x2 %0, %1, %2;" : "=l"(d) : "l"(a), "l"(b)); return d;
}
__device__ __forceinline__ ull add2(ull a, ull b) {
    ull d; asm("add.rn.f32x2 %0, %1, %2;" : "=l"(d) : "l"(a), "l"(b)); return d;
}
__device__ __forceinline__ float sqrta(float x) {
    float r; asm("sqrt.approx.f32 %0, %1;" : "=f"(r) : "f"(x)); return r;
}
__device__ __forceinline__ float ex2a(float x) {
    float r; asm("ex2.approx.f32 %0, %1;" : "=f"(r) : "f"(x)); return r;
}

__global__ __launch_bounds__(TPB)
void normals_renderer_kernel(const float* __restrict__ normals,
                             float* __restrict__ out)
{
    // SW*[k] = (v_k, v_{k XOR 256}) so a single LDS.64 yields the packed j-operand.
    __shared__ float2 swx[NPTS], swy[NPTS], swz[NPTS];   // 12 KB
    __shared__ float  gift[2][TPB * 3];                   // 6 KB, 12B slots (conflict-free)
    __shared__ float  sred[3][TPB / 32];

    const int b = blockIdx.x;
    const int t = threadIdx.x;

    const float* base = normals + (size_t)b * NPTS * 3;
    const float x0 = base[t * 3 + 0],          y0 = base[t * 3 + 1],          z0 = base[t * 3 + 2];
    const float x1 = base[(t + 256) * 3 + 0],  y1 = base[(t + 256) * 3 + 1],  z1 = base[(t + 256) * 3 + 2];

    swx[t] = make_float2(x0, x1);  swx[t + 256] = make_float2(x1, x0);
    swy[t] = make_float2(y0, y1);  swy[t + 256] = make_float2(y1, y0);
    swz[t] = make_float2(z0, z1);  swz[t + 256] = make_float2(z1, z0);
    __syncthreads();

    const ull xi2 = pack2(x0, x1), yi2 = pack2(y0, y1), zi2 = pack2(z0, z1);
    const ull q3v = pack2(Q3f, Q3f), q2v = pack2(Q2f, Q2f);
    const ull q1v = pack2(Q1f, Q1f), q0v = pack2(Q0f, Q0f);
    const ull lh2 = pack2(LHPIf, LHPIf);

    ull acc2 = pack2(0.0f, 0.0f);

    const ull* __restrict__ px = (const ull*)swx;
    const ull* __restrict__ py = (const ull*)swy;
    const ull* __restrict__ pz = (const ull*)swz;

    #define PAIR_BODY(K, BUF)                                                          \
    {                                                                                  \
        const int k_ = (K);                                                            \
        const ull njx = px[k_], njy = py[k_], njz = pz[k_];                            \
        ull d2 = fma2(zi2, njz, fma2(yi2, njy, mul2(xi2, njx)));                       \
        float da, db; unpack2(d2, da, db);                                             \
        float ua = __saturatef(1.0f - fabsf(da));                                      \
        float ub = __saturatef(1.0f - fabsf(db));                                      \
        float sa = sqrta(ua), sb = sqrta(ub);                                          \
        ull u2 = pack2(ua, ub);                                                        \
        ull p2 = fma2(u2, q3v, q2v);                                                   \
        p2 = fma2(u2, p2, q1v);                                                        \
        p2 = fma2(u2, p2, q0v);                                                        \
        ull g2 = fma2(pack2(sa, sb), p2, lh2);                                         \
        float ga, gb; unpack2(g2, ga, gb);                                             \
        unsigned int ea = __float_as_uint(ga) | (__float_as_uint(da) & 0x80000000u);   \
        unsigned int eb = __float_as_uint(gb) | (__float_as_uint(db) & 0x80000000u);   \
        float wa = ex2a(__uint_as_float(ea));                                          \
        float wb = ex2a(__uint_as_float(eb));                                          \
        acc2 = add2(acc2, pack2(wa, wb));                                              \
        const int m3 = (k_ & 255) * 3;                                                 \
        const int s_ = k_ >> 8;                                                        \
        gift[BUF][m3 + s_]       = wa;                                                 \
        gift[BUF][m3 + (s_ ^ 1)] = wb;                                                 \
        __syncthreads();                                                               \
        acc2 = add2(acc2, pack2(gift[BUF][t * 3], gift[BUF][t * 3 + 1]));              \
    }

    int k = t + 1;
    #pragma unroll 2
    for (int o = 1; o <= 254; o += 2) {
        PAIR_BODY(k, 0); k++;
        PAIR_BODY(k, 1); k++;
    }
    PAIR_BODY(k, 0);   // o = 255

    // o = 256: each thread's own two rows are each other's partner; weight added to both.
    {
        float d  = fmaf(z0, z1, fmaf(y0, y1, x0 * x1));
        float u  = __saturatef(1.0f - fabsf(d));
        float s  = sqrta(u);
        float p  = fmaf(u, Q3f, Q2f);
        p = fmaf(u, p, Q1f);
        p = fmaf(u, p, Q0f);
        float g  = fmaf(s, p, LHPIf);
        unsigned int e = __float_as_uint(g) | (__float_as_uint(d) & 0x80000000u);
        float w = ex2a(__uint_as_float(e));
        acc2 = add2(acc2, pack2(w, w));
    }

    // Weighted sum over this thread's two rows, then block reduction.
    float w0, w1; unpack2(acc2, w0, w1);
    float vx = fmaf(w1, x1, w0 * x0);
    float vy = fmaf(w1, y1, w0 * y0);
    float vz = fmaf(w1, z1, w0 * z0);

    #pragma unroll
    for (int s = 16; s >= 1; s >>= 1) {
        vx += __shfl_down_sync(0xffffffffu, vx, s);
        vy += __shfl_down_sync(0xffffffffu, vy, s);
        vz += __shfl_down_sync(0xffffffffu, vz, s);
    }
    const int lane = t & 31, warp = t >> 5;
    __syncthreads();   // protect gift reuse ordering / reduction scratch
    if (lane == 0) { sred[0][warp] = vx; sred[1][warp] = vy; sred[2][warp] = vz; }
    __syncthreads();

    if (warp == 0) {
        float rx = (lane < TPB / 32) ? sred[0][lane] : 0.0f;
        float ry = (lane < TPB / 32) ? sred[1][lane] : 0.0f;
        float rz = (lane < TPB / 32) ? sred[2][lane] : 0.0f;
        #pragma unroll
        for (int s = 4; s >= 1; s >>= 1) {
            rx += __shfl_down_sync(0xffffffffu, rx, s);
            ry += __shfl_down_sync(0xffffffffu, ry, s);
            rz += __shfl_down_sync(0xffffffffu, rz, s);
        }
        if (lane == 0) {
            float ss  = fmaf(rx, rx, fmaf(ry, ry, rz * rz));
            float inv = rsqrtf(fmaxf(ss, 1e-20f));
            out[b * 3 + 0] = rx * inv;
            out[b * 3 + 1] = ry * inv;
            out[b * 3 + 2] = rz * inv;
        }
    }
}

extern "C" void kernel_launch(void* const* d_in, const int* in_sizes, int n_in,
                              void* d_out, int out_size)
{
    const float* normals = (const float*)d_in[0];  // [512, 512, 3] f32
    // d_in[1] = weights: unused by the reference math.
    float* out = (float*)d_out;                    // [512, 3] f32

    normals_renderer_kernel<<<B_BATCH, TPB>>>(normals, out);
}

// round 4
// speedup vs baseline: 3.3023x; 1.2503x over previous
#include <cuda_runtime.h>
#include <cuda_bf16.h>

// NormalsRenderer: B=512, N=512.
// out[b] = normalize( sum_i acc_i * n_i ),  acc_i = sum_{j!=i} exp(-acos(clip(<n_i,n_j>)))
// Identities (uniform positive scales cancel under the final normalize):
//   - division by max(new_weights) dropped
//   - exp(-acos d) = e^{-pi/2} * exp(asin d); constant dropped
//   - u = sat(1-|d|);  asin(|d|)*log2e = LHPI + sqrt(u)*Q(u)  (cubic Q)
//   - w = exp2( copysign( LHPI + sqrt(u)*Q(u), d ) )
// Symmetry w_ij = w_ji via cyclic offsets: thread t owns rows (t, t+256); at offset o
// it evaluates pairs (t, t+o) and (t+256, (t+o)^256), accumulates locally and gifts
// the same weights to the partner rows through smem. Offsets split across 2 CTAs per
// batch (grid=1024); partial weighted sums combined + normalized by a tiny 2nd kernel.

#define NPTS 512
#define TPB  256
#define GPH  4          // offsets per gift phase (1 __syncthreads per phase)

typedef unsigned long long ull;
typedef unsigned int uint;

// -log2(e) * p_AS(1-u) re-expanded in u, and log2(e)*pi/2
#define Q0f (-2.0401824f)
#define Q1f (-0.17280645f)
#define Q2f (-0.026074023f)
#define Q3f (-0.027020667f)
#define LHPIf (2.2661800709f)

__device__ float g_stage[1024][3];   // per-CTA partial weighted sums

__device__ __forceinline__ ull pack2(float lo, float hi) {
    ull r; asm("mov.b64 %0, {%1, %2};" : "=l"(r) : "f"(lo), "f"(hi)); return r;
}
__device__ __forceinline__ void unpack2(ull v, float& lo, float& hi) {
    asm("mov.b64 {%0, %1}, %2;" : "=f"(lo), "=f"(hi) : "l"(v));
}
__device__ __forceinline__ ull fma2(ull a, ull b, ull c) {
    ull d; asm("fma.rn.f32x2 %0, %1, %2, %3;" : "=l"(d) : "l"(a), "l"(b), "l"(c)); return d;
}
__device__ __forceinline__ ull mul2(ull a, ull b) {
    ull d; asm("mul.rn.f32x2 %0, %1, %2;" : "=l"(d) : "l"(a), "l"(b)); return d;
}
__device__ __forceinline__ ull add2(ull a, ull b) {
    ull d; asm("add.rn.f32x2 %0, %1, %2;" : "=l"(d) : "l"(a), "l"(b)); return d;
}
__device__ __forceinline__ float sqrta(float x) {
    float r; asm("sqrt.approx.f32 %0, %1;" : "=f"(r) : "f"(x)); return r;
}
__device__ __forceinline__ float ex2a(float x) {
    float r; asm("ex2.approx.f32 %0, %1;" : "=f"(r) : "f"(x)); return r;
}

__global__ __launch_bounds__(TPB)
void normals_pair_kernel(const float* __restrict__ normals)
{
    // sw*[k] = (v_k, v_{k^256}): one LDS.64 yields the packed j-operand for both rows.
    __shared__ float2 swx[NPTS], swy[NPTS], swz[NPTS];     // 12 KB
    __shared__ float2 gift[2][GPH][TPB];                   // 16 KB, double-buffered
    __shared__ float  sred[3][TPB / 32];

    const int b    = blockIdx.x >> 1;
    const int half = blockIdx.x & 1;
    const int t    = threadIdx.x;

    const float* base = normals + (size_t)b * NPTS * 3;
    const float x0 = base[t * 3 + 0],         y0 = base[t * 3 + 1],         z0 = base[t * 3 + 2];
    const float x1 = base[(t + 256) * 3 + 0], y1 = base[(t + 256) * 3 + 1], z1 = base[(t + 256) * 3 + 2];

    swx[t] = make_float2(x0, x1);  swx[t + 256] = make_float2(x1, x0);
    swy[t] = make_float2(y0, y1);  swy[t + 256] = make_float2(y1, y0);
    swz[t] = make_float2(z0, z1);  swz[t + 256] = make_float2(z1, z0);
    __syncthreads();

    const ull xi2 = pack2(x0, x1), yi2 = pack2(y0, y1), zi2 = pack2(z0, z1);
    const ull q3v = pack2(Q3f, Q3f), q2v = pack2(Q2f, Q2f);
    const ull q1v = pack2(Q1f, Q1f), q0v = pack2(Q0f, Q0f);
    const ull lh2 = pack2(LHPIf, LHPIf);

    ull accA = pack2(0.0f, 0.0f);   // two accumulators to break the add chain
    ull accB = pack2(0.0f, 0.0f);

    const ull* __restrict__ px = (const ull*)swx;
    const ull* __restrict__ py = (const ull*)swy;
    const ull* __restrict__ pz = (const ull*)swz;

    // One pair-body: rows (t, t+256) vs rows (k, k^256). DO_GIFT=0 only for o=256
    // (self-partner pair: local accumulation alone is exactly right).
    #define PAIR_COMPUTE(K, GI, BUF, ACC, DO_GIFT)                                     \
    {                                                                                  \
        const int k_ = (K);                                                            \
        const ull njx = px[k_], njy = py[k_], njz = pz[k_];                            \
        ull d2 = fma2(zi2, njz, fma2(yi2, njy, mul2(xi2, njx)));                       \
        float da, db; unpack2(d2, da, db);                                             \
        float ua = __saturatef(1.0f - fabsf(da));                                      \
        float ub = __saturatef(1.0f - fabsf(db));                                      \
        float sa = sqrta(ua), sb = sqrta(ub);                                          \
        ull u2 = pack2(ua, ub);                                                        \
        ull p2 = fma2(u2, q3v, q2v);                                                   \
        p2 = fma2(u2, p2, q1v);                                                        \
        p2 = fma2(u2, p2, q0v);                                                        \
        ull g2 = fma2(pack2(sa, sb), p2, lh2);                                         \
        float ga, gb; unpack2(g2, ga, gb);                                             \
        uint ea = __float_as_uint(ga) | (__float_as_uint(da) & 0x80000000u);           \
        uint eb = __float_as_uint(gb) | (__float_as_uint(db) & 0x80000000u);           \
        float wa = ex2a(__uint_as_float(ea));                                          \
        float wb = ex2a(__uint_as_float(eb));                                          \
        ACC = add2(ACC, pack2(wa, wb));                                                \
        if (DO_GIFT) {                                                                 \
            const bool lo_ = k_ < 256;                                                 \
            float2 gv;                                                                 \
            gv.x = lo_ ? wa : wb;                                                      \
            gv.y = lo_ ? wb : wa;                                                      \
            gift[BUF][GI][k_ & 255] = gv;                                              \
        }                                                                              \
    }

    // half 0: o = 1..128 (32 full phases). half 1: o = 129..256 (31 full phases +
    // tail of 3 gifted bodies + 1 ungifted o=256 body).
    int k   = t + (half ? 129 : 1);
    int buf = 0;
    const int NP = half ? 31 : 32;

    #pragma unroll 1
    for (int p = 0; p < NP; ++p) {
        PAIR_COMPUTE(k + 0, 0, buf, accA, 1);
        PAIR_COMPUTE(k + 1, 1, buf, accB, 1);
        PAIR_COMPUTE(k + 2, 2, buf, accA, 1);
        PAIR_COMPUTE(k + 3, 3, buf, accB, 1);
        __syncthreads();
        {
            float2 r0 = gift[buf][0][t];
            float2 r1 = gift[buf][1][t];
            float2 r2 = gift[buf][2][t];
            float2 r3 = gift[buf][3][t];
            accA = add2(accA, pack2(r0.x, r0.y));
            accB = add2(accB, pack2(r1.x, r1.y));
            accA = add2(accA, pack2(r2.x, r2.y));
            accB = add2(accB, pack2(r3.x, r3.y));
        }
        buf ^= 1;
        k += GPH;
    }

    if (half) {   // tail: o = 253, 254, 255 gifted; o = 256 ungifted
        PAIR_COMPUTE(k + 0, 0, buf, accA, 1);
        PAIR_COMPUTE(k + 1, 1, buf, accB, 1);
        PAIR_COMPUTE(k + 2, 2, buf, accA, 1);
        PAIR_COMPUTE(k + 3, 3, buf, accB, 0);
        __syncthreads();
        {
            float2 r0 = gift[buf][0][t];
            float2 r1 = gift[buf][1][t];
            float2 r2 = gift[buf][2][t];
            accA = add2(accA, pack2(r0.x, r0.y));
            accB = add2(accB, pack2(r1.x, r1.y));
            accA = add2(accA, pack2(r2.x, r2.y));
        }
    }

    ull acc2 = add2(accA, accB);

    // Partial weighted sum over this thread's two rows, then block reduction.
    float w0, w1; unpack2(acc2, w0, w1);
    float vx = fmaf(w1, x1, w0 * x0);
    float vy = fmaf(w1, y1, w0 * y0);
    float vz = fmaf(w1, z1, w0 * z0);

    #pragma unroll
    for (int s = 16; s >= 1; s >>= 1) {
        vx += __shfl_down_sync(0xffffffffu, vx, s);
        vy += __shfl_down_sync(0xffffffffu, vy, s);
        vz += __shfl_down_sync(0xffffffffu, vz, s);
    }
    const int lane = t & 31, warp = t >> 5;
    if (lane == 0) { sred[0][warp] = vx; sred[1][warp] = vy; sred[2][warp] = vz; }
    __syncthreads();

    if (warp == 0) {
        float rx = (lane < TPB / 32) ? sred[0][lane] : 0.0f;
        float ry = (lane < TPB / 32) ? sred[1][lane] : 0.0f;
        float rz = (lane < TPB / 32) ? sred[2][lane] : 0.0f;
        #pragma unroll
        for (int s = 4; s >= 1; s >>= 1) {
            rx += __shfl_down_sync(0xffffffffu, rx, s);
            ry += __shfl_down_sync(0xffffffffu, ry, s);
            rz += __shfl_down_sync(0xffffffffu, rz, s);
        }
        if (lane == 0) {
            g_stage[blockIdx.x][0] = rx;
            g_stage[blockIdx.x][1] = ry;
            g_stage[blockIdx.x][2] = rz;
        }
    }
}

__global__ __launch_bounds__(256)
void normals_finalize_kernel(float* __restrict__ out)
{
    const int b = blockIdx.x * 256 + threadIdx.x;   // 0..511
    float rx = g_stage[2 * b][0] + g_stage[2 * b + 1][0];
    float ry = g_stage[2 * b][1] + g_stage[2 * b + 1][1];
    float rz = g_stage[2 * b][2] + g_stage[2 * b + 1][2];
    float ss  = fmaf(rx, rx, fmaf(ry, ry, rz * rz));
    float inv = rsqrtf(fmaxf(ss, 1e-20f));
    out[b * 3 + 0] = rx * inv;
    out[b * 3 + 1] = ry * inv;
    out[b * 3 + 2] = rz * inv;
}

extern "C" void kernel_launch(void* const* d_in, const int* in_sizes, int n_in,
                              void* d_out, int out_size)
{
    const float* normals = (const float*)d_in[0];  // [512, 512, 3] f32
    // d_in[1] = weights: unused by the reference math.
    float* out = (float*)d_out;                    // [512, 3] f32

    normals_pair_kernel<<<1024, TPB>>>(normals);
    normals_finalize_kernel<<<2, 256>>>(out);
}